// round 16
// baseline (speedup 1.0000x reference)
#include <cuda_runtime.h>
#include <cuda_fp16.h>
#include <math.h>

#define N_NODES 1048576
#define N_EDGES 4194304
#define EPSV 1e-5f
#define STATS_LEN (7*24 + 3*12)

// ---------------- scratch (static device globals; zero-init at load) ----------------
__device__ float  g_hA[N_NODES * 12];    // fp32 h: only conv8 output + head scratch
__device__ float  g_hB[N_NODES * 12];
__device__ __half g_hHA[N_NODES * 16];   // fp16 h (32B rows): conv-layer state
__device__ __half g_hHB[N_NODES * 16];
__device__ float4 g_xp[N_NODES];         // x packed to float4
__device__ int    g_deg[N_NODES];        // zeroed by k_scanA for next call
__device__ int    g_off[N_NODES + 1];
__device__ int    g_cur[N_NODES];
__device__ int    g_bsum[1024];
__device__ int    g_srt[N_EDGES];        // src ids grouped by dst (CSR adjacency)
__device__ float  g_stats[STATS_LEN];    // zeroed by k_scanB for next call

__device__ __forceinline__ float*  bufptr(int s)  { return s == 0 ? g_hA : g_hB; }
__device__ __forceinline__ __half* bufptrH(int s) { return s == 0 ? g_hHA : g_hHB; }

// ---- packed dual-fp32 FMA (Blackwell f32x2 pipe; exact fp32 on both lanes) ----
__device__ __forceinline__ unsigned long long pack2(float x, float y) {
    unsigned long long r;
    asm("mov.b64 %0, {%1, %2};" : "=l"(r) : "f"(x), "f"(y));
    return r;
}
__device__ __forceinline__ void unpack2(unsigned long long v, float& x, float& y) {
    asm("mov.b64 {%0, %1}, %2;" : "=f"(x), "=f"(y) : "l"(v));
}
__device__ __forceinline__ void fma2(unsigned long long& d, unsigned long long a,
                                     unsigned long long b) {
    asm("fma.rn.f32x2 %0, %1, %2, %3;" : "=l"(d) : "l"(a), "l"(b), "l"(d));
}

// ---- two-phase block stats reduction over 12 shared rows (stride-13 layout) ----
template <bool SQ>
__device__ __forceinline__ void stats_reduce(const float* sOut, int t, int base_out) {
    __syncthreads();
    if (t < 96) {
        int c = t >> 3, g = t & 7;
        float s = 0.f, q = 0.f;
#pragma unroll
        for (int jj = 0; jj < 32; jj++) {
            int j = (jj + 4 * g) & 31;
            float v = sOut[(g * 32 + j) * 13 + c];
            s += v;
            if (SQ) q += v * v;
        }
#pragma unroll
        for (int o = 4; o; o >>= 1) {
            s += __shfl_down_sync(0xffffffffu, s, o);
            if (SQ) q += __shfl_down_sync(0xffffffffu, q, o);
        }
        if (g == 0) {
            atomicAdd(&g_stats[base_out + c], s);
            if (SQ) atomicAdd(&g_stats[base_out + 12 + c], q);
        }
    }
}

// one 256-bit load of a 32B fp16 row -> 12 floats (words 6,7 padding)
__device__ __forceinline__ void loadH(float* dst, const __half* hH, int s) {
    const __half* r = hH + ((size_t)s << 4);
    float v0, v1, v2, v3, v4, v5, v6, v7;
    asm volatile("ld.global.nc.v8.f32 {%0,%1,%2,%3,%4,%5,%6,%7}, [%8];"
                 : "=f"(v0), "=f"(v1), "=f"(v2), "=f"(v3),
                   "=f"(v4), "=f"(v5), "=f"(v6), "=f"(v7)
                 : "l"(r));
    unsigned u;
    float2 f;
    u = __float_as_uint(v0); f = __half22float2(*reinterpret_cast<__half2*>(&u)); dst[0] = f.x; dst[1] = f.y;
    u = __float_as_uint(v1); f = __half22float2(*reinterpret_cast<__half2*>(&u)); dst[2] = f.x; dst[3] = f.y;
    u = __float_as_uint(v2); f = __half22float2(*reinterpret_cast<__half2*>(&u)); dst[4] = f.x; dst[5] = f.y;
    u = __float_as_uint(v3); f = __half22float2(*reinterpret_cast<__half2*>(&u)); dst[6] = f.x; dst[7] = f.y;
    u = __float_as_uint(v4); f = __half22float2(*reinterpret_cast<__half2*>(&u)); dst[8] = f.x; dst[9] = f.y;
    u = __float_as_uint(v5); f = __half22float2(*reinterpret_cast<__half2*>(&u)); dst[10] = f.x; dst[11] = f.y;
    (void)v6; (void)v7;
}

__device__ __forceinline__ void gathH(float* acc, const __half* hH, int s) {
    float tmp[12];
    loadH(tmp, hH, s);
#pragma unroll
    for (int j = 0; j < 12; j++) acc[j] += tmp[j];
}

// one 256-bit store of a 32B fp16 row (words 6,7 zero)
__device__ __forceinline__ void storeH(__half* hH, int i, const float* out) {
    __half* r = hH + ((size_t)i << 4);
    unsigned w0, w1, w2, w3, w4, w5;
    *reinterpret_cast<__half2*>(&w0) = __floats2half2_rn(out[0], out[1]);
    *reinterpret_cast<__half2*>(&w1) = __floats2half2_rn(out[2], out[3]);
    *reinterpret_cast<__half2*>(&w2) = __floats2half2_rn(out[4], out[5]);
    *reinterpret_cast<__half2*>(&w3) = __floats2half2_rn(out[6], out[7]);
    *reinterpret_cast<__half2*>(&w4) = __floats2half2_rn(out[8], out[9]);
    *reinterpret_cast<__half2*>(&w5) = __floats2half2_rn(out[10], out[11]);
    asm volatile("st.global.v8.f32 [%0], {%1,%2,%3,%4,%5,%6,%7,%8};"
                 :: "l"(r),
                    "f"(__uint_as_float(w0)), "f"(__uint_as_float(w1)),
                    "f"(__uint_as_float(w2)), "f"(__uint_as_float(w3)),
                    "f"(__uint_as_float(w4)), "f"(__uint_as_float(w5)),
                    "f"(0.f), "f"(0.f)
                 : "memory");
}

// ---------------- CSR build ----------------

__global__ void k_degx(const int* __restrict__ ei, const float* __restrict__ x) {
    int e = blockIdx.x * blockDim.x + threadIdx.x;
    if (e < N_EDGES) atomicAdd(&g_deg[__ldcs(&ei[N_EDGES + e])], 1);
    if (e < N_NODES) {
        g_xp[e] = make_float4(__ldcs(&x[3 * e]), __ldcs(&x[3 * e + 1]),
                              __ldcs(&x[3 * e + 2]), 0.f);
    }
}

__global__ void k_scanA() {
    __shared__ int sh[256];
    int t = threadIdx.x;
    int base = blockIdx.x * 1024 + t * 4;
    int4 d = *reinterpret_cast<int4*>(&g_deg[base]);
    *reinterpret_cast<int4*>(&g_deg[base]) = make_int4(0, 0, 0, 0);
    int s1 = d.x + d.y, s2 = s1 + d.z, tot = s2 + d.w;
    sh[t] = tot;
    __syncthreads();
#pragma unroll
    for (int o = 1; o < 256; o <<= 1) {
        int v = (t >= o) ? sh[t - o] : 0;
        __syncthreads();
        sh[t] += v;
        __syncthreads();
    }
    int excl = sh[t] - tot;
    g_off[base + 0] = excl;
    g_off[base + 1] = excl + d.x;
    g_off[base + 2] = excl + s1;
    g_off[base + 3] = excl + s2;
    if (t == 255) g_bsum[blockIdx.x] = sh[255];
}

__global__ void k_scanB() {
    __shared__ int sred[9];
    int t = threadIdx.x;
    if (blockIdx.x == 0 && t < STATS_LEN) g_stats[t] = 0.f;
    int q = blockIdx.x >> 2;
    int4 v = *reinterpret_cast<int4*>(&g_bsum[t * 4]);
    int j0 = t * 4;
    int s = (j0 + 0 < q ? v.x : 0) + (j0 + 1 < q ? v.y : 0)
          + (j0 + 2 < q ? v.z : 0) + (j0 + 3 < q ? v.w : 0);
#pragma unroll
    for (int o = 16; o; o >>= 1) s += __shfl_xor_sync(0xffffffffu, s, o);
    if ((t & 31) == 0) sred[t >> 5] = s;
    __syncthreads();
    if (t == 0) {
        int r0 = 0;
#pragma unroll
        for (int w = 0; w < 8; w++) r0 += sred[w];
        sred[8] = r0;
    }
    __syncthreads();
    int S = sred[8];
    int i = blockIdx.x * 256 + t;
    int val = g_off[i] + S;
    g_off[i] = val;
    g_cur[i] = val;
    if (i == 0) g_off[N_NODES] = N_EDGES;
}

__global__ void k_place(const int* __restrict__ ei) {
    int e = blockIdx.x * blockDim.x + threadIdx.x;
    if (e >= N_EDGES) return;
    int s = __ldcs(&ei[e]);
    int d = __ldcs(&ei[N_EDGES + e]);
    int p = atomicAdd(&g_cur[d], 1);
    g_srt[p] = s;
}

// ---------------- layer 1: float4-packed x gather; f32x2 GEMV ----------------
__global__ void k_node1f(const float* __restrict__ Wl1, const float* __restrict__ Wr1,
                         const float* __restrict__ b1) {
    __shared__ float2 sWl2[18], sWr2[18];   // [j*6+kp] = {W[2kp][j], W[2kp+1][j]}
    __shared__ float sb[12];
    __shared__ float sOut[256 * 13];
    int t = threadIdx.x;
    if (t < 18) {
        int j = t / 6, kp = t % 6;
        sWl2[t] = make_float2(Wl1[(2 * kp) * 3 + j], Wl1[(2 * kp + 1) * 3 + j]);
        sWr2[t] = make_float2(Wr1[(2 * kp) * 3 + j], Wr1[(2 * kp + 1) * 3 + j]);
    }
    if (t < 12) sb[t] = b1[t];
    __syncthreads();
    int i = blockIdx.x * blockDim.x + t;
    int beg = g_off[i], end = g_off[i + 1];
    float a0 = 0.f, a1 = 0.f, a2 = 0.f;
    int p = beg;
    for (; p + 2 <= end; p += 2) {
        int s0 = __ldg(&g_srt[p]), s1 = __ldg(&g_srt[p + 1]);
        float4 u = __ldg(&g_xp[s0]);
        float4 w = __ldg(&g_xp[s1]);
        a0 += u.x + w.x; a1 += u.y + w.y; a2 += u.z + w.z;
    }
    if (p < end) {
        float4 u = __ldg(&g_xp[__ldg(&g_srt[p])]);
        a0 += u.x; a1 += u.y; a2 += u.z;
    }
    int dg = end - beg;
    float inv = dg > 0 ? 1.f / (float)dg : 0.f;
    float mm[3] = {a0 * inv, a1 * inv, a2 * inv};
    float4 xs = __ldg(&g_xp[i]);
    float xx[3] = {xs.x, xs.y, xs.z};
    const unsigned long long* wl2 = reinterpret_cast<const unsigned long long*>(sWl2);
    const unsigned long long* wr2 = reinterpret_cast<const unsigned long long*>(sWr2);
    unsigned long long acc2[6];
#pragma unroll
    for (int kp = 0; kp < 6; kp++) acc2[kp] = pack2(sb[2 * kp], sb[2 * kp + 1]);
#pragma unroll
    for (int j = 0; j < 3; j++) {
        unsigned long long mj = pack2(mm[j], mm[j]);
        unsigned long long xj = pack2(xx[j], xx[j]);
#pragma unroll
        for (int kp = 0; kp < 6; kp++) {
            fma2(acc2[kp], mj, wl2[j * 6 + kp]);
            fma2(acc2[kp], xj, wr2[j * 6 + kp]);
        }
    }
    float out[12];
#pragma unroll
    for (int kp = 0; kp < 6; kp++) {
        float u, v;
        unpack2(acc2[kp], u, v);
        out[2 * kp]     = fmaxf(u, 0.f);
        out[2 * kp + 1] = fmaxf(v, 0.f);
    }
    storeH(g_hHA, i, out);
#pragma unroll
    for (int k = 0; k < 12; k++) sOut[t * 13 + k] = out[k];
    stats_reduce<true>(sOut, t, 0);
}

// ---------------- layers 2..8: all-fp16 state, f32x2 GEMV ----------------
template <int MODE>
__global__ void k_nodef(int in_sel, int out_sel,
                        const float* __restrict__ Wl, const float* __restrict__ Wr,
                        const float* __restrict__ bias,
                        const float* __restrict__ bng, const float* __restrict__ bnb,
                        int sin_off, int sout_off,
                        const float* __restrict__ linW, const float* __restrict__ linb) {
    const __half* hH_in = bufptrH(in_sel);
    float*  h_out  = bufptr(out_sel);
    __half* hH_out = bufptrH(out_sel);
    __shared__ float2 sWl2[72], sWr2[72];
    __shared__ float sb[12], sa[12], sc[12], sLW[36], sLB[6];
    __shared__ float sOut[256 * 13];
    int t = threadIdx.x;
    if (t < 72) {
        int j = t / 6, kp = t % 6;
        sWl2[t] = make_float2(Wl[(2 * kp) * 12 + j], Wl[(2 * kp + 1) * 12 + j]);
        sWr2[t] = make_float2(Wr[(2 * kp) * 12 + j], Wr[(2 * kp + 1) * 12 + j]);
    }
    if (t < 12) {
        sb[t] = bias[t];
        float mean = g_stats[sin_off + t] * (1.f / N_NODES);
        float var  = g_stats[sin_off + 12 + t] * (1.f / N_NODES) - mean * mean;
        float a = bng[t] * rsqrtf(var + EPSV);
        sa[t] = a;
        sc[t] = bnb[t] - mean * a;
    }
    if (MODE == 1) {
        if (t < 36) sLW[t] = linW[t];
        if (t < 6)  sLB[t] = linb[t];
    }
    __syncthreads();
    int i = blockIdx.x * blockDim.x + t;
    int beg = g_off[i], end = g_off[i + 1];
    float acc[12];
#pragma unroll
    for (int j = 0; j < 12; j++) acc[j] = 0.f;
    int p = beg;
    for (; p + 2 <= end; p += 2) {
        int s0 = __ldg(&g_srt[p]), s1 = __ldg(&g_srt[p + 1]);
        gathH(acc, hH_in, s0);
        gathH(acc, hH_in, s1);
    }
    if (p < end) gathH(acc, hH_in, __ldg(&g_srt[p]));

    float hv[12];
    loadH(hv, hH_in, i);            // self row from fp16 mirror (1 wavefront)
    int dg = end - beg;
    float gate = dg > 0 ? 1.f : 0.f;
    float inv  = dg > 0 ? 1.f / (float)dg : 0.f;
    float m[12], hb[12];
#pragma unroll
    for (int j = 0; j < 12; j++) {
        m[j]  = acc[j] * inv * sa[j] + sc[j] * gate;   // bn(mean) fold; isolated -> 0
        hb[j] = hv[j] * sa[j] + sc[j];
    }
    const unsigned long long* wl2 = reinterpret_cast<const unsigned long long*>(sWl2);
    const unsigned long long* wr2 = reinterpret_cast<const unsigned long long*>(sWr2);
    unsigned long long acc2[6];
#pragma unroll
    for (int kp = 0; kp < 6; kp++) acc2[kp] = pack2(sb[2 * kp], sb[2 * kp + 1]);
#pragma unroll
    for (int j = 0; j < 12; j++) {
        unsigned long long mj = pack2(m[j], m[j]);
        unsigned long long hj = pack2(hb[j], hb[j]);
#pragma unroll
        for (int kp = 0; kp < 6; kp++) {
            fma2(acc2[kp], mj, wl2[j * 6 + kp]);
            fma2(acc2[kp], hj, wr2[j * 6 + kp]);
        }
    }
    float out[12];
#pragma unroll
    for (int kp = 0; kp < 6; kp++) {
        float u, v;
        unpack2(acc2[kp], u, v);
        out[2 * kp]     = fmaxf(u, 0.f);
        out[2 * kp + 1] = fmaxf(v, 0.f);
    }
    if (MODE == 0) {
        storeH(hH_out, i, out);
#pragma unroll
        for (int k = 0; k < 12; k++) sOut[t * 13 + k] = out[k];
        stats_reduce<true>(sOut, t, sout_off);
    } else {
        float4* op = reinterpret_cast<float4*>(h_out + (size_t)i * 12);
        __stcs(op + 0, make_float4(out[0], out[1], out[2], out[3]));
        __stcs(op + 1, make_float4(out[4], out[5], out[6], out[7]));
        __stcs(op + 2, make_float4(out[8], out[9], out[10], out[11]));
#pragma unroll
        for (int k = 0; k < 6; k++) {
            float za = sLB[k], zb = sLB[k];
#pragma unroll
            for (int j = 0; j < 6; j++) { za += out[j] * sLW[6 * k + j]; zb += out[6 + j] * sLW[6 * k + j]; }
            sOut[t * 13 + k]     = za + zb;
            sOut[t * 13 + 6 + k] = za * za + zb * zb;
        }
        stats_reduce<false>(sOut, t, sout_off);
    }
}

// ---------------- head: two [.,6] halves paired in f32x2 lanes ----------------
template <int PASS>
__global__ void k_head(int in_sel, int out_sel,
                       const float* __restrict__ linW, const float* __restrict__ linb,
                       const float* __restrict__ g6, const float* __restrict__ b6,
                       int sin_off, int sout_off,
                       const float* __restrict__ oW, const float* __restrict__ ob,
                       float* __restrict__ outp) {
    const float* h_in = bufptr(in_sel);
    float* h_out = bufptr(out_sel);
    __shared__ float2 sLW2[36];   // [k*6+j] = {w, w} duplicated for lane pair
    __shared__ float sLB[6], sa[6], sc[6], sOW[7];
    __shared__ float sOut[256 * 13];
    int t = threadIdx.x;
    if (t < 36) { float w = linW[t]; sLW2[t] = make_float2(w, w); }
    if (t < 6) {
        sLB[t] = linb[t];
        const float invM = 1.f / (2.f * N_NODES);
        float mean = g_stats[sin_off + t] * invM;
        float var  = g_stats[sin_off + 6 + t] * invM - mean * mean;
        float a = g6[t] * rsqrtf(var + EPSV);
        sa[t] = a;
        sc[t] = b6[t] - mean * a;
    }
    if (PASS == 3) { if (t < 6) sOW[t] = oW[t]; if (t == 6) sOW[6] = ob[0]; }
    __syncthreads();
    int i = blockIdx.x * blockDim.x + t;
    const float4* hp = reinterpret_cast<const float4*>(h_in + (size_t)i * 12);
    float4 h0 = __ldcs(hp + 0), h1 = __ldcs(hp + 1), h2 = __ldcs(hp + 2);
    float hv[12] = {h0.x, h0.y, h0.z, h0.w, h1.x, h1.y, h1.z, h1.w, h2.x, h2.y, h2.z, h2.w};
    const unsigned long long* lw2 = reinterpret_cast<const unsigned long long*>(sLW2);
    // z for both halves: lane0 = half0, lane1 = half1
    unsigned long long z2[6];
#pragma unroll
    for (int k = 0; k < 6; k++) z2[k] = pack2(sLB[k], sLB[k]);
#pragma unroll
    for (int j = 0; j < 6; j++) {
        unsigned long long hj = pack2(hv[j], hv[6 + j]);
#pragma unroll
        for (int k = 0; k < 6; k++) fma2(z2[k], hj, lw2[k * 6 + j]);
    }
    float r[12];
#pragma unroll
    for (int k = 0; k < 6; k++) {
        float za, zb;
        unpack2(z2[k], za, zb);
        r[k]     = fmaxf(za * sa[k] + sc[k], 0.f);
        r[6 + k] = fmaxf(zb * sa[k] + sc[k], 0.f);
    }
    if (PASS < 3) {
        float4* op = reinterpret_cast<float4*>(h_out + (size_t)i * 12);
        __stcs(op + 0, make_float4(r[0], r[1], r[2], r[3]));
        __stcs(op + 1, make_float4(r[4], r[5], r[6], r[7]));
        __stcs(op + 2, make_float4(r[8], r[9], r[10], r[11]));
        // z_next for both halves, paired
        unsigned long long y2[6];
#pragma unroll
        for (int k = 0; k < 6; k++) y2[k] = pack2(sLB[k], sLB[k]);
#pragma unroll
        for (int j = 0; j < 6; j++) {
            unsigned long long rj = pack2(r[j], r[6 + j]);
#pragma unroll
            for (int k = 0; k < 6; k++) fma2(y2[k], rj, lw2[k * 6 + j]);
        }
#pragma unroll
        for (int k = 0; k < 6; k++) {
            float za, zb;
            unpack2(y2[k], za, zb);
            sOut[t * 13 + k]     = za + zb;
            sOut[t * 13 + 6 + k] = za * za + zb * zb;
        }
        stats_reduce<false>(sOut, t, sout_off);
    } else {
        unsigned long long o2 = pack2(sOW[6], sOW[6]);
#pragma unroll
        for (int j = 0; j < 6; j++) {
            unsigned long long rj = pack2(r[j], r[6 + j]);
            unsigned long long wj = pack2(sOW[j], sOW[j]);
            fma2(o2, rj, wj);
        }
        float oa, obv;
        unpack2(o2, oa, obv);
        outp[2 * i]     = 1.f / (1.f + expf(-oa));
        outp[2 * i + 1] = 1.f / (1.f + expf(-obv));
    }
}

// ---------------- launch ----------------
extern "C" void kernel_launch(void* const* d_in, const int* in_sizes, int n_in,
                              void* d_out, int out_size) {
    const float* x    = (const float*)d_in[0];
    const int*   ei   = (const int*)d_in[1];
    const float* Wl1  = (const float*)d_in[2];
    const float* Wr1  = (const float*)d_in[3];
    const float* b1   = (const float*)d_in[4];
    const float* Wl   = (const float*)d_in[5];
    const float* Wr   = (const float*)d_in[6];
    const float* bb   = (const float*)d_in[7];
    const float* bng  = (const float*)d_in[8];
    const float* bnb  = (const float*)d_in[9];
    const float* linW = (const float*)d_in[10];
    const float* linb = (const float*)d_in[11];
    const float* g6   = (const float*)d_in[12];
    const float* b6   = (const float*)d_in[13];
    const float* oW   = (const float*)d_in[14];
    const float* ob   = (const float*)d_in[15];
    float* outp = (float*)d_out;

    const int EB = N_EDGES / 256;   // 16384
    const int NB = N_NODES / 256;   // 4096

    // CSR build (g_deg/g_stats zero at entry: load-time init or fused re-zeroing)
    k_degx<<<EB, 256>>>(ei, x);
    k_scanA<<<1024, 256>>>();       // also re-zeroes g_deg for next call
    k_scanB<<<NB, 256>>>();         // block 0 also re-zeroes g_stats
    k_place<<<EB, 256>>>(ei);

    // conv1 -> hHA (fp16), stats slot 0
    k_node1f<<<NB, 256>>>(Wl1, Wr1, b1);

    int in_sel = 0, out_sel = 1;
    for (int i = 0; i < 7; i++) {
        int sin_off = 24 * i;
        if (i < 6) {
            k_nodef<0><<<NB, 256>>>(in_sel, out_sel, Wl + 144 * i, Wr + 144 * i, bb + 12 * i,
                                    bng + 12 * i, bnb + 12 * i, sin_off, 24 * (i + 1),
                                    linW, linb);
        } else {
            k_nodef<1><<<NB, 256>>>(in_sel, out_sel, Wl + 144 * i, Wr + 144 * i, bb + 12 * i,
                                    bng + 12 * i, bnb + 12 * i, sin_off, 7 * 24,
                                    linW, linb);
        }
        int tmp = in_sel; in_sel = out_sel; out_sel = tmp;
    }
    // conv8 output (fp32) in g_hB. Head: hB -> hA -> hB -> out.
    k_head<1><<<NB, 256>>>(1, 0, linW, linb, g6, b6, 168, 180, oW, ob, outp);
    k_head<2><<<NB, 256>>>(0, 1, linW, linb, g6, b6, 180, 192, oW, ob, outp);
    k_head<3><<<NB, 256>>>(1, 0, linW, linb, g6, b6, 192, 0, oW, ob, outp);
}

// round 17
// speedup vs baseline: 1.0388x; 1.0388x over previous
#include <cuda_runtime.h>
#include <cuda_fp16.h>
#include <math.h>

#define N_NODES 1048576
#define N_EDGES 4194304
#define EPSV 1e-5f
#define STATS_LEN (7*24 + 3*12)

// ---------------- scratch (static device globals; zero-init at load) ----------------
__device__ float  g_hA[N_NODES * 12];    // fp32 h: only conv8 output + head scratch
__device__ float  g_hB[N_NODES * 12];
__device__ __half g_hHA[N_NODES * 16];   // fp16 h (32B rows): conv-layer state
__device__ __half g_hHB[N_NODES * 16];
__device__ float4 g_xp[N_NODES];         // x packed to float4
__device__ int    g_deg[N_NODES];        // zeroed by k_scanA for next call
__device__ int    g_off[N_NODES + 1];
__device__ int    g_cur[N_NODES];
__device__ int    g_bsum[1024];
__device__ int    g_srt[N_EDGES];        // src ids grouped by dst (CSR adjacency)
__device__ float  g_stats[STATS_LEN];    // zeroed by k_scanB for next call

__device__ __forceinline__ float*  bufptr(int s)  { return s == 0 ? g_hA : g_hB; }
__device__ __forceinline__ __half* bufptrH(int s) { return s == 0 ? g_hHA : g_hHB; }

// ---- packed dual-fp32 FMA (Blackwell f32x2 pipe; exact fp32 on both lanes) ----
__device__ __forceinline__ unsigned long long pack2(float x, float y) {
    unsigned long long r;
    asm("mov.b64 %0, {%1, %2};" : "=l"(r) : "f"(x), "f"(y));
    return r;
}
__device__ __forceinline__ void unpack2(unsigned long long v, float& x, float& y) {
    asm("mov.b64 {%0, %1}, %2;" : "=f"(x), "=f"(y) : "l"(v));
}
__device__ __forceinline__ void fma2(unsigned long long& d, unsigned long long a,
                                     unsigned long long b) {
    asm("fma.rn.f32x2 %0, %1, %2, %3;" : "=l"(d) : "l"(a), "l"(b), "l"(d));
}

// ---- two-phase block stats reduction over 12 shared rows (stride-13 layout) ----
template <bool SQ>
__device__ __forceinline__ void stats_reduce(const float* sOut, int t, int base_out) {
    __syncthreads();
    if (t < 96) {
        int c = t >> 3, g = t & 7;
        float s = 0.f, q = 0.f;
#pragma unroll
        for (int jj = 0; jj < 32; jj++) {
            int j = (jj + 4 * g) & 31;
            float v = sOut[(g * 32 + j) * 13 + c];
            s += v;
            if (SQ) q += v * v;
        }
#pragma unroll
        for (int o = 4; o; o >>= 1) {
            s += __shfl_down_sync(0xffffffffu, s, o);
            if (SQ) q += __shfl_down_sync(0xffffffffu, q, o);
        }
        if (g == 0) {
            atomicAdd(&g_stats[base_out + c], s);
            if (SQ) atomicAdd(&g_stats[base_out + 12 + c], q);
        }
    }
}

// one 256-bit load of a 32B fp16 row -> 12 floats (words 6,7 padding)
__device__ __forceinline__ void loadH(float* dst, const __half* hH, int s) {
    const __half* r = hH + ((size_t)s << 4);
    float v0, v1, v2, v3, v4, v5, v6, v7;
    asm volatile("ld.global.nc.v8.f32 {%0,%1,%2,%3,%4,%5,%6,%7}, [%8];"
                 : "=f"(v0), "=f"(v1), "=f"(v2), "=f"(v3),
                   "=f"(v4), "=f"(v5), "=f"(v6), "=f"(v7)
                 : "l"(r));
    unsigned u;
    float2 f;
    u = __float_as_uint(v0); f = __half22float2(*reinterpret_cast<__half2*>(&u)); dst[0] = f.x; dst[1] = f.y;
    u = __float_as_uint(v1); f = __half22float2(*reinterpret_cast<__half2*>(&u)); dst[2] = f.x; dst[3] = f.y;
    u = __float_as_uint(v2); f = __half22float2(*reinterpret_cast<__half2*>(&u)); dst[4] = f.x; dst[5] = f.y;
    u = __float_as_uint(v3); f = __half22float2(*reinterpret_cast<__half2*>(&u)); dst[6] = f.x; dst[7] = f.y;
    u = __float_as_uint(v4); f = __half22float2(*reinterpret_cast<__half2*>(&u)); dst[8] = f.x; dst[9] = f.y;
    u = __float_as_uint(v5); f = __half22float2(*reinterpret_cast<__half2*>(&u)); dst[10] = f.x; dst[11] = f.y;
    (void)v6; (void)v7;
}

__device__ __forceinline__ void gathH(float* acc, const __half* hH, int s) {
    float tmp[12];
    loadH(tmp, hH, s);
#pragma unroll
    for (int j = 0; j < 12; j++) acc[j] += tmp[j];
}

// one 256-bit store of a 32B fp16 row (words 6,7 zero)
__device__ __forceinline__ void storeH(__half* hH, int i, const float* out) {
    __half* r = hH + ((size_t)i << 4);
    unsigned w0, w1, w2, w3, w4, w5;
    *reinterpret_cast<__half2*>(&w0) = __floats2half2_rn(out[0], out[1]);
    *reinterpret_cast<__half2*>(&w1) = __floats2half2_rn(out[2], out[3]);
    *reinterpret_cast<__half2*>(&w2) = __floats2half2_rn(out[4], out[5]);
    *reinterpret_cast<__half2*>(&w3) = __floats2half2_rn(out[6], out[7]);
    *reinterpret_cast<__half2*>(&w4) = __floats2half2_rn(out[8], out[9]);
    *reinterpret_cast<__half2*>(&w5) = __floats2half2_rn(out[10], out[11]);
    asm volatile("st.global.v8.f32 [%0], {%1,%2,%3,%4,%5,%6,%7,%8};"
                 :: "l"(r),
                    "f"(__uint_as_float(w0)), "f"(__uint_as_float(w1)),
                    "f"(__uint_as_float(w2)), "f"(__uint_as_float(w3)),
                    "f"(__uint_as_float(w4)), "f"(__uint_as_float(w5)),
                    "f"(0.f), "f"(0.f)
                 : "memory");
}

// ---------------- CSR build ----------------

// pure degree histogram (x packing moved to k_place's idle issue slots)
__global__ void k_degx(const int* __restrict__ ei) {
    int e = blockIdx.x * blockDim.x + threadIdx.x;
    if (e < N_EDGES) atomicAdd(&g_deg[__ldcs(&ei[N_EDGES + e])], 1);
}

__global__ void k_scanA() {
    __shared__ int sh[256];
    int t = threadIdx.x;
    int base = blockIdx.x * 1024 + t * 4;
    int4 d = *reinterpret_cast<int4*>(&g_deg[base]);
    *reinterpret_cast<int4*>(&g_deg[base]) = make_int4(0, 0, 0, 0);
    int s1 = d.x + d.y, s2 = s1 + d.z, tot = s2 + d.w;
    sh[t] = tot;
    __syncthreads();
#pragma unroll
    for (int o = 1; o < 256; o <<= 1) {
        int v = (t >= o) ? sh[t - o] : 0;
        __syncthreads();
        sh[t] += v;
        __syncthreads();
    }
    int excl = sh[t] - tot;
    g_off[base + 0] = excl;
    g_off[base + 1] = excl + d.x;
    g_off[base + 2] = excl + s1;
    g_off[base + 3] = excl + s2;
    if (t == 255) g_bsum[blockIdx.x] = sh[255];
}

__global__ void k_scanB() {
    __shared__ int sred[9];
    int t = threadIdx.x;
    if (blockIdx.x == 0 && t < STATS_LEN) g_stats[t] = 0.f;
    int q = blockIdx.x >> 2;
    int4 v = *reinterpret_cast<int4*>(&g_bsum[t * 4]);
    int j0 = t * 4;
    int s = (j0 + 0 < q ? v.x : 0) + (j0 + 1 < q ? v.y : 0)
          + (j0 + 2 < q ? v.z : 0) + (j0 + 3 < q ? v.w : 0);
#pragma unroll
    for (int o = 16; o; o >>= 1) s += __shfl_xor_sync(0xffffffffu, s, o);
    if ((t & 31) == 0) sred[t >> 5] = s;
    __syncthreads();
    if (t == 0) {
        int r0 = 0;
#pragma unroll
        for (int w = 0; w < 8; w++) r0 += sred[w];
        sred[8] = r0;
    }
    __syncthreads();
    int S = sred[8];
    int i = blockIdx.x * 256 + t;
    int val = g_off[i] + S;
    g_off[i] = val;
    g_cur[i] = val;
    if (i == 0) g_off[N_NODES] = N_EDGES;
}

// edge placement + x packing (packing rides in place's idle issue slots)
__global__ void k_place(const int* __restrict__ ei, const float* __restrict__ x) {
    int e = blockIdx.x * blockDim.x + threadIdx.x;
    if (e < N_NODES) {
        g_xp[e] = make_float4(__ldcs(&x[3 * e]), __ldcs(&x[3 * e + 1]),
                              __ldcs(&x[3 * e + 2]), 0.f);
    }
    if (e >= N_EDGES) return;
    int s = __ldcs(&ei[e]);
    int d = __ldcs(&ei[N_EDGES + e]);
    int p = atomicAdd(&g_cur[d], 1);
    g_srt[p] = s;
}

// ---------------- layer 1: float4-packed x gather; scalar GEMV (R15 form) -------
__global__ void k_node1f(const float* __restrict__ Wl1, const float* __restrict__ Wr1,
                         const float* __restrict__ b1) {
    __shared__ float sWl[36], sWr[36], sb[12];
    __shared__ float sOut[256 * 13];
    int t = threadIdx.x;
    if (t < 36) { sWl[t] = Wl1[t]; sWr[t] = Wr1[t]; }
    if (t < 12) sb[t] = b1[t];
    __syncthreads();
    int i = blockIdx.x * blockDim.x + t;
    int beg = g_off[i], end = g_off[i + 1];
    float a0 = 0.f, a1 = 0.f, a2 = 0.f;
    int p = beg;
    for (; p + 2 <= end; p += 2) {
        int s0 = __ldg(&g_srt[p]), s1 = __ldg(&g_srt[p + 1]);
        float4 u = __ldg(&g_xp[s0]);
        float4 w = __ldg(&g_xp[s1]);
        a0 += u.x + w.x; a1 += u.y + w.y; a2 += u.z + w.z;
    }
    if (p < end) {
        float4 u = __ldg(&g_xp[__ldg(&g_srt[p])]);
        a0 += u.x; a1 += u.y; a2 += u.z;
    }
    int dg = end - beg;
    float inv = dg > 0 ? 1.f / (float)dg : 0.f;
    float m0 = a0 * inv, m1 = a1 * inv, m2 = a2 * inv;
    float4 xs = __ldg(&g_xp[i]);
    float out[12];
#pragma unroll
    for (int k = 0; k < 12; k++) {
        float v = sb[k] + m0 * sWl[3 * k] + m1 * sWl[3 * k + 1] + m2 * sWl[3 * k + 2]
                        + xs.x * sWr[3 * k] + xs.y * sWr[3 * k + 1] + xs.z * sWr[3 * k + 2];
        out[k] = fmaxf(v, 0.f);
    }
    storeH(g_hHA, i, out);
#pragma unroll
    for (int k = 0; k < 12; k++) sOut[t * 13 + k] = out[k];
    stats_reduce<true>(sOut, t, 0);
}

// ---------------- layers 2..8: all-fp16 state, f32x2 GEMV ----------------
template <int MODE>
__global__ void k_nodef(int in_sel, int out_sel,
                        const float* __restrict__ Wl, const float* __restrict__ Wr,
                        const float* __restrict__ bias,
                        const float* __restrict__ bng, const float* __restrict__ bnb,
                        int sin_off, int sout_off,
                        const float* __restrict__ linW, const float* __restrict__ linb) {
    const __half* hH_in = bufptrH(in_sel);
    float*  h_out  = bufptr(out_sel);
    __half* hH_out = bufptrH(out_sel);
    __shared__ float2 sWl2[72], sWr2[72];
    __shared__ float sb[12], sa[12], sc[12], sLW[36], sLB[6];
    __shared__ float sOut[256 * 13];
    int t = threadIdx.x;
    if (t < 72) {
        int j = t / 6, kp = t % 6;
        sWl2[t] = make_float2(Wl[(2 * kp) * 12 + j], Wl[(2 * kp + 1) * 12 + j]);
        sWr2[t] = make_float2(Wr[(2 * kp) * 12 + j], Wr[(2 * kp + 1) * 12 + j]);
    }
    if (t < 12) {
        sb[t] = bias[t];
        float mean = g_stats[sin_off + t] * (1.f / N_NODES);
        float var  = g_stats[sin_off + 12 + t] * (1.f / N_NODES) - mean * mean;
        float a = bng[t] * rsqrtf(var + EPSV);
        sa[t] = a;
        sc[t] = bnb[t] - mean * a;
    }
    if (MODE == 1) {
        if (t < 36) sLW[t] = linW[t];
        if (t < 6)  sLB[t] = linb[t];
    }
    __syncthreads();
    int i = blockIdx.x * blockDim.x + t;
    int beg = g_off[i], end = g_off[i + 1];
    float acc[12];
#pragma unroll
    for (int j = 0; j < 12; j++) acc[j] = 0.f;
    int p = beg;
    for (; p + 2 <= end; p += 2) {
        int s0 = __ldg(&g_srt[p]), s1 = __ldg(&g_srt[p + 1]);
        gathH(acc, hH_in, s0);
        gathH(acc, hH_in, s1);
    }
    if (p < end) gathH(acc, hH_in, __ldg(&g_srt[p]));

    float hv[12];
    loadH(hv, hH_in, i);            // self row from fp16 mirror (1 wavefront)
    int dg = end - beg;
    float gate = dg > 0 ? 1.f : 0.f;
    float inv  = dg > 0 ? 1.f / (float)dg : 0.f;
    float m[12], hb[12];
#pragma unroll
    for (int j = 0; j < 12; j++) {
        m[j]  = acc[j] * inv * sa[j] + sc[j] * gate;   // bn(mean) fold; isolated -> 0
        hb[j] = hv[j] * sa[j] + sc[j];
    }
    const unsigned long long* wl2 = reinterpret_cast<const unsigned long long*>(sWl2);
    const unsigned long long* wr2 = reinterpret_cast<const unsigned long long*>(sWr2);
    unsigned long long acc2[6];
#pragma unroll
    for (int kp = 0; kp < 6; kp++) acc2[kp] = pack2(sb[2 * kp], sb[2 * kp + 1]);
#pragma unroll
    for (int j = 0; j < 12; j++) {
        unsigned long long mj = pack2(m[j], m[j]);
        unsigned long long hj = pack2(hb[j], hb[j]);
#pragma unroll
        for (int kp = 0; kp < 6; kp++) {
            fma2(acc2[kp], mj, wl2[j * 6 + kp]);
            fma2(acc2[kp], hj, wr2[j * 6 + kp]);
        }
    }
    float out[12];
#pragma unroll
    for (int kp = 0; kp < 6; kp++) {
        float u, v;
        unpack2(acc2[kp], u, v);
        out[2 * kp]     = fmaxf(u, 0.f);
        out[2 * kp + 1] = fmaxf(v, 0.f);
    }
    if (MODE == 0) {
        storeH(hH_out, i, out);
#pragma unroll
        for (int k = 0; k < 12; k++) sOut[t * 13 + k] = out[k];
        stats_reduce<true>(sOut, t, sout_off);
    } else {
        float4* op = reinterpret_cast<float4*>(h_out + (size_t)i * 12);
        __stcs(op + 0, make_float4(out[0], out[1], out[2], out[3]));
        __stcs(op + 1, make_float4(out[4], out[5], out[6], out[7]));
        __stcs(op + 2, make_float4(out[8], out[9], out[10], out[11]));
#pragma unroll
        for (int k = 0; k < 6; k++) {
            float za = sLB[k], zb = sLB[k];
#pragma unroll
            for (int j = 0; j < 6; j++) { za += out[j] * sLW[6 * k + j]; zb += out[6 + j] * sLW[6 * k + j]; }
            sOut[t * 13 + k]     = za + zb;
            sOut[t * 13 + 6 + k] = za * za + zb * zb;
        }
        stats_reduce<false>(sOut, t, sout_off);
    }
}

// ---------------- head (all fp32, streaming; scalar GEMV — R15 form) ------------
template <int PASS>
__global__ void k_head(int in_sel, int out_sel,
                       const float* __restrict__ linW, const float* __restrict__ linb,
                       const float* __restrict__ g6, const float* __restrict__ b6,
                       int sin_off, int sout_off,
                       const float* __restrict__ oW, const float* __restrict__ ob,
                       float* __restrict__ outp) {
    const float* h_in = bufptr(in_sel);
    float* h_out = bufptr(out_sel);
    __shared__ float sLW[36], sLB[6], sa[6], sc[6], sOW[7];
    __shared__ float sOut[256 * 13];
    int t = threadIdx.x;
    if (t < 36) sLW[t] = linW[t];
    if (t < 6) {
        sLB[t] = linb[t];
        const float invM = 1.f / (2.f * N_NODES);
        float mean = g_stats[sin_off + t] * invM;
        float var  = g_stats[sin_off + 6 + t] * invM - mean * mean;
        float a = g6[t] * rsqrtf(var + EPSV);
        sa[t] = a;
        sc[t] = b6[t] - mean * a;
    }
    if (PASS == 3) { if (t < 6) sOW[t] = oW[t]; if (t == 6) sOW[6] = ob[0]; }
    __syncthreads();
    int i = blockIdx.x * blockDim.x + t;
    const float4* hp = reinterpret_cast<const float4*>(h_in + (size_t)i * 12);
    float4 h0 = __ldcs(hp + 0), h1 = __ldcs(hp + 1), h2 = __ldcs(hp + 2);
    float hv[12] = {h0.x, h0.y, h0.z, h0.w, h1.x, h1.y, h1.z, h1.w, h2.x, h2.y, h2.z, h2.w};
    float r[12];
#pragma unroll
    for (int half = 0; half < 2; half++) {
#pragma unroll
        for (int k = 0; k < 6; k++) {
            float z = sLB[k];
#pragma unroll
            for (int j = 0; j < 6; j++) z += hv[6 * half + j] * sLW[6 * k + j];
            r[6 * half + k] = fmaxf(z * sa[k] + sc[k], 0.f);
        }
    }
    if (PASS < 3) {
        float4* op = reinterpret_cast<float4*>(h_out + (size_t)i * 12);
        __stcs(op + 0, make_float4(r[0], r[1], r[2], r[3]));
        __stcs(op + 1, make_float4(r[4], r[5], r[6], r[7]));
        __stcs(op + 2, make_float4(r[8], r[9], r[10], r[11]));
#pragma unroll
        for (int k = 0; k < 6; k++) {
            float za = sLB[k], zb = sLB[k];
#pragma unroll
            for (int j = 0; j < 6; j++) { za += r[j] * sLW[6 * k + j]; zb += r[6 + j] * sLW[6 * k + j]; }
            sOut[t * 13 + k]     = za + zb;
            sOut[t * 13 + 6 + k] = za * za + zb * zb;
        }
        stats_reduce<false>(sOut, t, sout_off);
    } else {
        float oa = sOW[6], obv = sOW[6];
#pragma unroll
        for (int j = 0; j < 6; j++) { oa += r[j] * sOW[j]; obv += r[6 + j] * sOW[j]; }
        outp[2 * i]     = 1.f / (1.f + expf(-oa));
        outp[2 * i + 1] = 1.f / (1.f + expf(-obv));
    }
}

// ---------------- launch ----------------
extern "C" void kernel_launch(void* const* d_in, const int* in_sizes, int n_in,
                              void* d_out, int out_size) {
    const float* x    = (const float*)d_in[0];
    const int*   ei   = (const int*)d_in[1];
    const float* Wl1  = (const float*)d_in[2];
    const float* Wr1  = (const float*)d_in[3];
    const float* b1   = (const float*)d_in[4];
    const float* Wl   = (const float*)d_in[5];
    const float* Wr   = (const float*)d_in[6];
    const float* bb   = (const float*)d_in[7];
    const float* bng  = (const float*)d_in[8];
    const float* bnb  = (const float*)d_in[9];
    const float* linW = (const float*)d_in[10];
    const float* linb = (const float*)d_in[11];
    const float* g6   = (const float*)d_in[12];
    const float* b6   = (const float*)d_in[13];
    const float* oW   = (const float*)d_in[14];
    const float* ob   = (const float*)d_in[15];
    float* outp = (float*)d_out;

    const int EB = N_EDGES / 256;   // 16384
    const int NB = N_NODES / 256;   // 4096

    // CSR build (g_deg/g_stats zero at entry: load-time init or fused re-zeroing)
    k_degx<<<EB, 256>>>(ei);
    k_scanA<<<1024, 256>>>();       // also re-zeroes g_deg for next call
    k_scanB<<<NB, 256>>>();         // block 0 also re-zeroes g_stats
    k_place<<<EB, 256>>>(ei, x);    // also packs x into g_xp (idle issue slots)

    // conv1 -> hHA (fp16), stats slot 0
    k_node1f<<<NB, 256>>>(Wl1, Wr1, b1);

    int in_sel = 0, out_sel = 1;
    for (int i = 0; i < 7; i++) {
        int sin_off = 24 * i;
        if (i < 6) {
            k_nodef<0><<<NB, 256>>>(in_sel, out_sel, Wl + 144 * i, Wr + 144 * i, bb + 12 * i,
                                    bng + 12 * i, bnb + 12 * i, sin_off, 24 * (i + 1),
                                    linW, linb);
        } else {
            k_nodef<1><<<NB, 256>>>(in_sel, out_sel, Wl + 144 * i, Wr + 144 * i, bb + 12 * i,
                                    bng + 12 * i, bnb + 12 * i, sin_off, 7 * 24,
                                    linW, linb);
        }
        int tmp = in_sel; in_sel = out_sel; out_sel = tmp;
    }
    // conv8 output (fp32) in g_hB. Head: hB -> hA -> hB -> out.
    k_head<1><<<NB, 256>>>(1, 0, linW, linb, g6, b6, 168, 180, oW, ob, outp);
    k_head<2><<<NB, 256>>>(0, 1, linW, linb, g6, b6, 180, 192, oW, ob, outp);
    k_head<3><<<NB, 256>>>(1, 0, linW, linb, g6, b6, 192, 0, oW, ob, outp);
}